// round 2
// baseline (speedup 1.0000x reference)
#include <cuda_runtime.h>
#include <math.h>

#define BB 32
#define LL 4096
#define DD 1024
#define SPLITS 16
#define CHUNK (LL / SPLITS)   // 256 rows per block
#define NTHREADS 256
#define RGROUP 8
#define NEG_INF_F (-1e30f)

// Scratch (allocation-free rule: __device__ globals)
__device__ float g_scores[BB * LL];                 // raw masked scores (512 KB)
__device__ float g_pm[BB * SPLITS];                 // per-split running max
__device__ float g_ps[BB * SPLITS];                 // per-split running sum
__device__ float g_pacc[(size_t)BB * SPLITS * DD];  // per-split weighted acc (2 MB)

__global__ __launch_bounds__(NTHREADS)
void uda_pass1(const float* __restrict__ seq,
               const float* __restrict__ vec,
               const int* __restrict__ mask) {
    const int blk   = blockIdx.x;        // b*SPLITS + split
    const int b     = blk / SPLITS;
    const int split = blk % SPLITS;
    const int l0    = split * CHUNK;
    const int tid   = threadIdx.x;
    const int wid   = tid >> 5;
    const int lane  = tid & 31;

    __shared__ float sm_part[RGROUP][NTHREADS];   // 8 KB
    __shared__ float sm_score[RGROUP];

    // Each thread owns 4 consecutive d-values (float4).
    const float4 v4 = reinterpret_cast<const float4*>(vec + (size_t)b * DD)[tid];

    float m = -INFINITY;
    float s = 0.0f;
    float4 acc = make_float4(0.f, 0.f, 0.f, 0.f);

    const float4* seqp = reinterpret_cast<const float4*>(seq + (size_t)b * LL * DD);
    const int* mrow = mask + (size_t)b * LL;

    for (int g = 0; g < CHUNK; g += RGROUP) {
        // Load 8 rows' worth of this thread's float4 (MLP=8)
        float4 x[RGROUP];
#pragma unroll
        for (int i = 0; i < RGROUP; i++)
            x[i] = seqp[(size_t)(l0 + g + i) * (DD / 4) + tid];

        // Partial dot products into shared
#pragma unroll
        for (int i = 0; i < RGROUP; i++)
            sm_part[i][tid] = x[i].x * v4.x + x[i].y * v4.y + x[i].z * v4.z + x[i].w * v4.w;
        __syncthreads();

        // Warp `wid` reduces row `wid` (8 warps <-> 8 rows), conflict-free reads
        {
            float r = 0.0f;
#pragma unroll
            for (int k = 0; k < NTHREADS / 32; k++)
                r += sm_part[wid][lane + 32 * k];
#pragma unroll
            for (int off = 16; off; off >>= 1)
                r += __shfl_xor_sync(0xffffffffu, r, off);
            if (lane == 0) {
                const int row = l0 + g + wid;
                if (mrow[row] == 0) r = NEG_INF_F;
                sm_score[wid] = r;
                g_scores[(size_t)b * LL + row] = r;   // for weights output
            }
        }
        __syncthreads();

        // Online softmax update (replicated, deterministic across all threads)
        float sc[RGROUP];
        float mnew = m;
#pragma unroll
        for (int i = 0; i < RGROUP; i++) {
            sc[i] = sm_score[i];
            mnew = fmaxf(mnew, sc[i]);
        }
        const float f = __expf(m - mnew);   // exp(-inf - finite) = 0 handles init
        s *= f;
        acc.x *= f; acc.y *= f; acc.z *= f; acc.w *= f;
#pragma unroll
        for (int i = 0; i < RGROUP; i++) {
            const float w = __expf(sc[i] - mnew);
            s += w;
            acc.x += w * x[i].x;
            acc.y += w * x[i].y;
            acc.z += w * x[i].z;
            acc.w += w * x[i].w;
        }
        m = mnew;
        // No extra sync needed: next iter's sm_part/sm_score writes are
        // separated from this iter's reads by the next iter's first sync
        // (sm_score) and this iter's second sync (sm_part).
    }

    if (tid == 0) { g_pm[blk] = m; g_ps[blk] = s; }
    reinterpret_cast<float4*>(g_pacc + (size_t)blk * DD)[tid] = acc;
}

__global__ __launch_bounds__(NTHREADS)
void uda_pass2(float* __restrict__ out) {
    const int b   = blockIdx.x;
    const int tid = threadIdx.x;

    // Global max / sum across splits (tiny, replicated per thread)
    float pm[SPLITS];
    float M = -INFINITY;
#pragma unroll
    for (int i = 0; i < SPLITS; i++) {
        pm[i] = g_pm[b * SPLITS + i];
        M = fmaxf(M, pm[i]);
    }
    float S = 0.0f;
    float fac[SPLITS];
#pragma unroll
    for (int i = 0; i < SPLITS; i++) {
        fac[i] = __expf(pm[i] - M);
        S += g_ps[b * SPLITS + i] * fac[i];
    }
    const float invS = 1.0f / S;

    // pooled[b, :]  (output region 0: B*D floats)
    float4 acc = make_float4(0.f, 0.f, 0.f, 0.f);
#pragma unroll
    for (int i = 0; i < SPLITS; i++) {
        const float4 p =
            reinterpret_cast<const float4*>(g_pacc + (size_t)(b * SPLITS + i) * DD)[tid];
        const float f = fac[i];
        acc.x += f * p.x; acc.y += f * p.y; acc.z += f * p.z; acc.w += f * p.w;
    }
    acc.x *= invS; acc.y *= invS; acc.z *= invS; acc.w *= invS;
    reinterpret_cast<float4*>(out + (size_t)b * DD)[tid] = acc;

    // weights[b, :]  (output region 1: B*L floats, after pooled)
    float* wout = out + (size_t)BB * DD + (size_t)b * LL;
    const float* srow = g_scores + (size_t)b * LL;
    for (int l = tid; l < LL; l += NTHREADS)
        wout[l] = __expf(srow[l] - M) * invS;
}

extern "C" void kernel_launch(void* const* d_in, const int* in_sizes, int n_in,
                              void* d_out, int out_size) {
    const float* seq  = (const float*)d_in[0];
    const float* vec  = (const float*)d_in[1];
    const int*   mask = (const int*)d_in[2];
    float* out = (float*)d_out;

    uda_pass1<<<BB * SPLITS, NTHREADS>>>(seq, vec, mask);
    uda_pass2<<<BB, NTHREADS>>>(out);
}